// round 15
// baseline (speedup 1.0000x reference)
#include <cuda_runtime.h>
#include <cuda_bf16.h>
#include <cstdint>

#define BB 1024
#define SS 512
#define TT 48
#define FULL 0xFFFFFFFFu
#define LN2 0.69314718055994530942

typedef unsigned long long ull;

__device__ double g_scratch[BB];
__device__ unsigned int g_count = 0;
__device__ int g_len[BB];
__device__ int g_perm[BB];
__device__ float g_hv[BB][2][48];     // per-batch fwd/bwd half state vectors
__device__ float g_hsref[BB];         // fwd shift
__device__ int   g_hesum[BB][2];      // power-of-2 rescale exponents
__device__ float g_gold[BB];

__device__ __forceinline__ ull pack2f(float a, float b) {
    ull r;
    asm("mov.b64 %0, {%1, %2};" : "=l"(r) : "f"(a), "f"(b));
    return r;
}
__device__ __forceinline__ void unpack2f(ull v, float& lo, float& hi) {
    asm("mov.b64 {%0, %1}, %2;" : "=f"(lo), "=f"(hi) : "l"(v));
}
__device__ __forceinline__ void fma2(ull& acc, ull a, ull b) {
    asm("fma.rn.f32x2 %0, %1, %2, %0;" : "+l"(acc) : "l"(a), "l"(b));
}
__device__ __forceinline__ ull add2(ull a, ull b) {
    ull r;
    asm("add.rn.f32x2 %0, %1, %2;" : "=l"(r) : "l"(a), "l"(b));
    return r;
}
__device__ __forceinline__ float hsum2(ull a, ull b) {
    ull u = add2(a, b);
    float lo, hi;
    unpack2f(u, lo, hi);
    return lo + hi;
}
__device__ __forceinline__ float warp_sum_f(float v) {
    #pragma unroll
    for (int o = 16; o; o >>= 1) v += __shfl_xor_sync(FULL, v, o);
    return v;
}
#define STS(a_, v_) asm volatile("st.shared.f32 [%0], %1;" :: "r"(a_), "f"(v_))

// ---------- prepass: lengths (binary search) + counting sort ----------
extern "C" __global__ void __launch_bounds__(1024)
prep_kernel(const float* __restrict__ mask) {
    const int b = threadIdx.x;
    int lo = 0, hi = SS;
    #pragma unroll
    for (int it = 0; it < 9; it++) {
        int mid = (lo + hi) >> 1;
        bool one = __ldg(&mask[b * SS + mid]) > 0.5f;
        lo = one ? mid : lo;
        hi = one ? hi : mid;
    }
    const int len = lo + 1;
    g_len[b] = len;

    __shared__ int cnt[SS + 1];
    __shared__ int scn[SS + 1];
    if (threadIdx.x <= SS) cnt[threadIdx.x] = 0;
    __syncthreads();
    atomicAdd(&cnt[len], 1);
    __syncthreads();
    if (threadIdx.x <= SS) scn[threadIdx.x] = cnt[threadIdx.x];
    __syncthreads();
    #pragma unroll
    for (int off = 1; off <= SS; off <<= 1) {
        int v = 0;
        if (threadIdx.x <= SS && threadIdx.x >= off) v = scn[threadIdx.x - off];
        __syncthreads();
        if (threadIdx.x <= SS) scn[threadIdx.x] += v;
        __syncthreads();
    }
    if (threadIdx.x <= SS) cnt[threadIdx.x] = scn[threadIdx.x] - cnt[threadIdx.x];
    __syncthreads();
    int r = atomicAdd(&cnt[len], 1);
    g_perm[r] = b;                      // ascending by length
}

// ---- one recurrence step for slot S (A or B); R11 matvec body, runtime parity ----
#define STEPK(S, ex_, ey_, ez_) do {                                            \
    const unsigned rb_ = pb##S + par##S;                                        \
    const unsigned wb_ = pb##S + (par##S ^ 512u);                               \
    float ceA_ = __expf(ex_);                                                   \
    float ceB_ = __expf(ey_);                                                   \
    float ceC_ = __expf(ez_);                                                   \
    if ((s##S & 3) == 0) {                                                      \
        float r0_;                                                              \
        asm volatile("ld.shared.f32 %0, [%1];" : "=f"(r0_) : "r"(rb_));         \
        int e_ = ((__float_as_int(r0_) >> 23) & 0xFF) - 127;                    \
        float sc_ = __int_as_float((127 - e_) << 23);                           \
        ceA_ *= sc_; ceB_ *= sc_; ceC_ *= sc_;                                  \
        esum##S += e_;                                                          \
    }                                                                           \
    ull a0_ = 0ull, a1_ = 0ull, b0_ = 0ull, b1_ = 0ull, c0_ = 0ull, c1_ = 0ull; \
    const unsigned lo_ = rb_ + rb4;                                             \
    _Pragma("unroll")                                                           \
    for (int c = 0; c < 3; c++) {                                               \
        ull P0, P1, P2, P3;                                                     \
        asm volatile("ld.shared.v2.u64 {%0, %1}, [%2];"                         \
            : "=l"(P0), "=l"(P1) : "r"(lo_ + c * 32));                          \
        asm volatile("ld.shared.v2.u64 {%0, %1}, [%2];"                         \
            : "=l"(P2), "=l"(P3) : "r"(lo_ + c * 32 + 16));                     \
        fma2(a0_, P0, EA[4*c  ]); fma2(b0_, P0, EB[4*c  ]); fma2(c0_, P0, EC[4*c  ]); \
        fma2(a1_, P1, EA[4*c+1]); fma2(b1_, P1, EB[4*c+1]); fma2(c1_, P1, EC[4*c+1]); \
        fma2(a0_, P2, EA[4*c+2]); fma2(b0_, P2, EB[4*c+2]); fma2(c0_, P2, EC[4*c+2]); \
        fma2(a1_, P3, EA[4*c+3]); fma2(b1_, P3, EB[4*c+3]); fma2(c1_, P3, EC[4*c+3]); \
    }                                                                           \
    float qA_ = hsum2(a0_, a1_) * ceA_;                                         \
    float qB_ = hsum2(b0_, b1_) * ceB_;                                         \
    float qC_ = hsum2(c0_, c1_) * ceC_;                                         \
    qA_ += __shfl_xor_sync(FULL, qA_, 16);                                      \
    qB_ += __shfl_xor_sync(FULL, qB_, 16);                                      \
    qC_ += __shfl_xor_sync(FULL, qC_, 16);                                      \
    p##S##A = qA_; p##S##B = qB_; p##S##C = qC_;                                \
    const unsigned st_ = wb_ + stoff;                                           \
    STS(st_, qA_); STS(st_ + 64, qB_); STS(st_ + 128, qC_);                     \
    par##S ^= 512u;                                                             \
    s##S++;                                                                     \
} while (0)

// emission fetch for step q_ of slot S (branchless):
// fwd: row q_ (clamped); bwd: row len-1-q_ (clamped), zeroed at q_ >= ns (unit ce)
#define LD3S(S, q_, x_, y_, z_) do {                                            \
    int qc_ = min((int)(q_), ns##S);                                            \
    int row_ = isfwd ? qc_ : (len##S - 1 - qc_);                                \
    const float* pp_ = emp##S + (long)row_ * TT;                                \
    float xv_ = __ldg(pp_ + cA), yv_ = __ldg(pp_ + cB), zv_ = __ldg(pp_ + cC);  \
    bool kp_ = isfwd || ((int)(q_) < ns##S);                                    \
    x_ = kp_ ? xv_ : 0.f; y_ = kp_ ? yv_ : 0.f; z_ = kp_ ? zv_ : 0.f;           \
} while (0)

// advance slot S to its next job (init state, gold for fwd, prime e-pipeline)
#define NEXTJOB(S, R0_, R1_) do {                                               \
    int r_ = (ji##S == 0) ? (R0_) : ((ji##S == 1) ? (R1_) : -1);                \
    ji##S++;                                                                    \
    if (r_ < 0) { act##S = 0; }                                                 \
    else {                                                                      \
        act##S = 1;                                                             \
        batch##S = g_perm[1023 - r_];                                           \
        len##S   = g_len[batch##S];                                             \
        ns##S    = isfwd ? (len##S >> 1) : (len##S - 1 - (len##S >> 1));        \
        emp##S   = em + (long)batch##S * SS * TT;                               \
        s##S = 1; par##S = 0u; esum##S = 0;                                     \
        if (isfwd) {                                                            \
            float g_ = 0.f;                                                     \
            for (int it_ = 0; it_ < SS / 32; it_++) {                           \
                int t_ = lane + it_ * 32;                                       \
                if (t_ < len##S) {                                              \
                    int tg_ = tags[batch##S * SS + t_];                         \
                    if (t_ == 0) g_ += __ldg(&startt[tg_]) + __ldg(emp##S + tg_); \
                    else {                                                      \
                        int tp_ = tags[batch##S * SS + t_ - 1];                 \
                        g_ += __ldg(&trans[tg_ * TT + tp_])                     \
                            + __ldg(emp##S + (long)t_ * TT + tg_);              \
                    }                                                           \
                    if (t_ == len##S - 1) g_ += __ldg(&endt[tg_]);              \
                }                                                               \
            }                                                                   \
            float gold_ = warp_sum_f(g_);                                       \
            if (lane == 0) g_gold[batch##S] = gold_;                            \
            float a_ = __ldg(&startt[cA]) + __ldg(emp##S + cA);                 \
            float b_ = __ldg(&startt[cB]) + __ldg(emp##S + cB);                 \
            float c_ = __ldg(&startt[cC]) + __ldg(emp##S + cC);                 \
            sref##S = __shfl_sync(FULL, a_, 0);                                 \
            p##S##A = __expf(a_ - sref##S);                                     \
            p##S##B = __expf(b_ - sref##S);                                     \
            p##S##C = __expf(c_ - sref##S);                                     \
        } else {                                                                \
            float eN0_ = 0.f, eN1_ = 0.f, eN2_ = 0.f;                           \
            if (ns##S > 0) {                                                    \
                const float* q_ = emp##S + (long)(len##S - 1) * TT;             \
                eN0_ = __ldg(q_ + cA); eN1_ = __ldg(q_ + cB); eN2_ = __ldg(q_ + cC); \
            }                                                                   \
            p##S##A = __expf(__ldg(&endt[cA]) + eN0_);                          \
            p##S##B = __expf(__ldg(&endt[cB]) + eN1_);                          \
            p##S##C = __expf(__ldg(&endt[cC]) + eN2_);                          \
            sref##S = 0.f;                                                      \
        }                                                                       \
        const unsigned s0_ = pb##S + stoff;                                     \
        STS(s0_, p##S##A); STS(s0_ + 64, p##S##B); STS(s0_ + 128, p##S##C);     \
        LD3S(S, 1, e##S##0x, e##S##0y, e##S##0z);                               \
        LD3S(S, 2, e##S##1x, e##S##1y, e##S##1z);                               \
    }                                                                           \
} while (0)

#define FINALJOB(S) do {                                                        \
    if (lane < 16) {                                                            \
        float* hv_ = &g_hv[batch##S][hix][0];                                   \
        hv_[cA] = p##S##A; hv_[cB] = p##S##B; hv_[cC] = p##S##C;                \
    }                                                                           \
    if (lane == 0) {                                                            \
        g_hesum[batch##S][hix] = esum##S;                                       \
        if (isfwd) g_hsref[batch##S] = sref##S;                                 \
    }                                                                           \
} while (0)

// one slot-step + e-pipeline rotation
#define SLOTSTEP(S) do {                                                        \
    STEPK(S, e##S##0x, e##S##0y, e##S##0z);                                     \
    float nx_, ny_, nz_;                                                        \
    LD3S(S, s##S + 1, nx_, ny_, nz_);                                           \
    e##S##0x = e##S##1x; e##S##0y = e##S##1y; e##S##0z = e##S##1z;              \
    e##S##1x = nx_;      e##S##1y = ny_;      e##S##1z = nz_;                   \
} while (0)

// 148 blocks x 128 threads: 1 warp/SMSP. Warps 0..295 = forward halves,
// 296..591 = backward halves (E transposed, shared by both slots). Each warp
// interleaves TWO half-jobs (dual-slot) so their serial chains overlap.
// Zig-zag job ranks give ~216-256 steps per slot, ~432-472 per warp.
extern "C" __global__ void __launch_bounds__(128)
half_kernel(const float* __restrict__ em,
            const int*   __restrict__ tags,
            const float* __restrict__ trans,
            const float* __restrict__ startt,
            const float* __restrict__ endt)
{
    const int lane = threadIdx.x & 31;
    const int wid  = threadIdx.x >> 5;
    const int w    = blockIdx.x * 4 + wid;        // 0..591
    const bool isfwd = (w < 296);
    const int m = isfwd ? w : (w - 296);
    const int hix = isfwd ? 0 : 1;

    __shared__ __align__(16) float p_buf[4][2][2][128]; // [warp][slot][parity][128f]

    const int j     = lane & 15;
    const int half  = lane >> 4;
    const int rbase = half * 24;
    const unsigned rb4 = (unsigned)(rbase * 4);
    const int cA = j, cB = j + 16, cC = j + 32;
    const unsigned stoff = (unsigned)(half * 256 + j * 4);

    // E: fwd uses exp(trans[r][c]) (contract prev); bwd uses exp(trans[c][r])
    ull EA[12], EB[12], EC[12];
    #pragma unroll
    for (int kk = 0; kk < 12; kk++) {
        int r0 = rbase + 2 * kk, r1 = r0 + 1;
        int iA0 = isfwd ? (r0 * TT + cA) : (cA * TT + r0);
        int iA1 = isfwd ? (r1 * TT + cA) : (cA * TT + r1);
        int iB0 = isfwd ? (r0 * TT + cB) : (cB * TT + r0);
        int iB1 = isfwd ? (r1 * TT + cB) : (cB * TT + r1);
        int iC0 = isfwd ? (r0 * TT + cC) : (cC * TT + r0);
        int iC1 = isfwd ? (r1 * TT + cC) : (cC * TT + r1);
        EA[kk] = pack2f(__expf(__ldg(&trans[iA0])), __expf(__ldg(&trans[iA1])));
        EB[kk] = pack2f(__expf(__ldg(&trans[iB0])), __expf(__ldg(&trans[iB1])));
        EC[kk] = pack2f(__expf(__ldg(&trans[iC0])), __expf(__ldg(&trans[iC1])));
    }

    const unsigned smb = (unsigned)__cvta_generic_to_shared(&p_buf[wid][0][0][0]);
    const unsigned pbA = smb;
    const unsigned pbB = smb + 1024u;

    // zig-zag desc-rank job lists (constant slot sums ~216)
    const int rA0 = m;
    const int rA1 = (m >= 160) ? (1183 - m) : -1;
    const int rB0 = 591 - m;
    const int rB1 = 592 + m;

    // slot state
    int batchA, lenA, nsA, sA, esumA, jiA = 0, actA;
    int batchB, lenB, nsB, sB, esumB, jiB = 0, actB;
    unsigned parA, parB;
    float pAA, pAB, pAC, srefA, pBA, pBB, pBC, srefB;
    const float *empA, *empB;
    float eA0x, eA0y, eA0z, eA1x, eA1y, eA1z;
    float eB0x, eB0y, eB0z, eB1x, eB1y, eB1z;

    NEXTJOB(A, rA0, rA1);
    NEXTJOB(B, rB0, rB1);

    // dual interleave while both slots live
    while (actA && actB) {
        int remA = nsA - sA + 1;
        int remB = nsB - sB + 1;
        int n = remA < remB ? remA : remB;
        #pragma unroll 1
        for (int i = 0; i < n; i++) {
            SLOTSTEP(A);
            SLOTSTEP(B);
        }
        if (sA > nsA) { FINALJOB(A); NEXTJOB(A, rA0, rA1); }
        if (actB && sB > nsB) { FINALJOB(B); NEXTJOB(B, rB0, rB1); }
    }
    // drain remaining slot(s)
    while (actA) {
        int n = nsA - sA + 1;
        #pragma unroll 1
        for (int i = 0; i < n; i++) SLOTSTEP(A);
        FINALJOB(A); NEXTJOB(A, rA0, rA1);
    }
    while (actB) {
        int n = nsB - sB + 1;
        #pragma unroll 1
        for (int i = 0; i < n; i++) SLOTSTEP(B);
        FINALJOB(B); NEXTJOB(B, rB0, rB1);
    }
}

// combine: logZ = sref_f + (esum_f+esum_b)*ln2 + log(sum_j pf_j*pb_j); mean reduce
extern "C" __global__ void __launch_bounds__(128)
comb_kernel(float* __restrict__ out) {
    const int lane = threadIdx.x & 31;
    const int wid  = threadIdx.x >> 5;
    const int b    = blockIdx.x * 4 + wid;   // 0..1023 (grid 256)

    float v = 0.f;
    if (lane < 16) {
        const float* pf = &g_hv[b][0][0];
        const float* pbv = &g_hv[b][1][0];
        int c0 = lane, c1 = lane + 16, c2 = lane + 32;
        v = pf[c0] * pbv[c0] + pf[c1] * pbv[c1] + pf[c2] * pbv[c2];
    }
    float ssum = warp_sum_f(v);
    if (lane == 0) {
        double logz = (double)g_hsref[b]
                    + (double)(g_hesum[b][0] + g_hesum[b][1]) * LN2
                    + (double)__logf(ssum);
        g_scratch[b] = logz - (double)g_gold[b];
    }

    __syncthreads();
    __shared__ bool is_last;
    if (threadIdx.x == 0) {
        __threadfence();
        unsigned r = atomicAdd(&g_count, 1u);
        is_last = (r == gridDim.x - 1);
    }
    __syncthreads();
    if (is_last) {
        __threadfence();
        double s = 0.0;
        for (int i = threadIdx.x; i < BB; i += 128) s += g_scratch[i];
        __shared__ double sh[128];
        sh[threadIdx.x] = s;
        __syncthreads();
        #pragma unroll
        for (int o = 64; o; o >>= 1) {
            if (threadIdx.x < o) sh[threadIdx.x] += sh[threadIdx.x + o];
            __syncthreads();
        }
        if (threadIdx.x == 0) {
            out[0] = (float)(sh[0] / (double)BB);
            g_count = 0;   // reset for next graph replay
        }
    }
}

extern "C" void kernel_launch(void* const* d_in, const int* in_sizes, int n_in,
                              void* d_out, int out_size) {
    const float* em     = (const float*)d_in[0];
    const int*   tags   = (const int*)d_in[1];
    const float* mask   = (const float*)d_in[2];
    const float* trans  = (const float*)d_in[3];
    const float* startt = (const float*)d_in[4];
    const float* endt   = (const float*)d_in[5];
    float* out = (float*)d_out;

    prep_kernel<<<1, 1024>>>(mask);
    half_kernel<<<148, 128>>>(em, tags, trans, startt, endt);
    comb_kernel<<<256, 128>>>(out);
}

// round 16
// speedup vs baseline: 1.8872x; 1.8872x over previous
#include <cuda_runtime.h>
#include <cuda_bf16.h>
#include <cstdint>

#define BB 1024
#define SS 512
#define TT 48
#define FULL 0xFFFFFFFFu
#define NPAIR 432          // warps 0..431 run two batches; 432..591 run one
#define LN2 0.69314718055994530942

typedef unsigned long long ull;

__device__ double g_scratch[BB];
__device__ unsigned int g_count = 0;
__device__ int g_len[BB];
__device__ int g_perm[BB];

__device__ __forceinline__ ull pack2f(float a, float b) {
    ull r;
    asm("mov.b64 %0, {%1, %2};" : "=l"(r) : "f"(a), "f"(b));
    return r;
}
__device__ __forceinline__ void unpack2f(ull v, float& lo, float& hi) {
    asm("mov.b64 {%0, %1}, %2;" : "=f"(lo), "=f"(hi) : "l"(v));
}
__device__ __forceinline__ void fma2(ull& acc, ull a, ull b) {
    asm("fma.rn.f32x2 %0, %1, %2, %0;" : "+l"(acc) : "l"(a), "l"(b));
}
__device__ __forceinline__ ull add2(ull a, ull b) {
    ull r;
    asm("add.rn.f32x2 %0, %1, %2;" : "=l"(r) : "l"(a), "l"(b));
    return r;
}
__device__ __forceinline__ float hsum2(ull a, ull b) {
    ull u = add2(a, b);
    float lo, hi;
    unpack2f(u, lo, hi);
    return lo + hi;
}
__device__ __forceinline__ float warp_sum_f(float v) {
    #pragma unroll
    for (int o = 16; o; o >>= 1) v += __shfl_xor_sync(FULL, v, o);
    return v;
}

// ---------- fused prepass: lengths (binary search) + counting sort ----------
extern "C" __global__ void __launch_bounds__(1024)
prep_kernel(const float* __restrict__ mask) {
    const int b = threadIdx.x;          // 1024 threads = 1024 batches
    int lo = 0, hi = SS;
    #pragma unroll
    for (int it = 0; it < 9; it++) {    // 2^9 = 512
        int mid = (lo + hi) >> 1;
        bool one = __ldg(&mask[b * SS + mid]) > 0.5f;
        lo = one ? mid : lo;
        hi = one ? hi : mid;
    }
    const int len = lo + 1;
    g_len[b] = len;

    __shared__ int cnt[SS + 1];
    __shared__ int scn[SS + 1];
    if (threadIdx.x <= SS) cnt[threadIdx.x] = 0;
    __syncthreads();
    atomicAdd(&cnt[len], 1);
    __syncthreads();
    if (threadIdx.x <= SS) scn[threadIdx.x] = cnt[threadIdx.x];
    __syncthreads();
    // Hillis-Steele inclusive scan over 513 entries
    #pragma unroll
    for (int off = 1; off <= SS; off <<= 1) {
        int v = 0;
        if (threadIdx.x <= SS && threadIdx.x >= off) v = scn[threadIdx.x - off];
        __syncthreads();
        if (threadIdx.x <= SS) scn[threadIdx.x] += v;
        __syncthreads();
    }
    if (threadIdx.x <= SS) cnt[threadIdx.x] = scn[threadIdx.x] - cnt[threadIdx.x]; // exclusive
    __syncthreads();
    int r = atomicAdd(&cnt[len], 1);
    g_perm[r] = b;                      // ascending by length
}

// One recurrence step (round-11 body, exact). Writer-side combine: lane l and
// l+16 own the same 3 columns; each sums its 24-row half, then shfl.xor(16)+add
// merges halves. Single combined p array in smem (hi half stores to shadow).
// Rescale every 4 steps by exact power-of-2 (exponent bits); esum exact int.
#define STEPX(pA_, pB_, pC_, exA_, exB_, exC_, RBOFF_, WBOFF_, DORESC_, t_) do { \
    const unsigned rb_ = pbufb + (RBOFF_);                                      \
    const unsigned wb_ = pbufb + (WBOFF_);                                      \
    float ceA_ = __expf(exA_);                                                  \
    float ceB_ = __expf(exB_);                                                  \
    float ceC_ = __expf(exC_);                                                  \
    if (DORESC_ && (((t_) & 3) == 0)) {                                         \
        float r0_;                                                              \
        asm volatile("ld.shared.f32 %0, [%1];" : "=f"(r0_) : "r"(rb_));         \
        int e_ = ((__float_as_int(r0_) >> 23) & 0xFF) - 127;                    \
        float sc_ = __int_as_float((127 - e_) << 23);                           \
        ceA_ *= sc_; ceB_ *= sc_; ceC_ *= sc_;                                  \
        esum += e_;                                                             \
    }                                                                           \
    ull a0_ = 0ull, a1_ = 0ull, b0_ = 0ull, b1_ = 0ull, c0_ = 0ull, c1_ = 0ull; \
    const unsigned lo_ = rb_ + rb4;                                             \
    _Pragma("unroll")                                                           \
    for (int c = 0; c < 3; c++) {                                               \
        ull P0, P1, P2, P3;                                                     \
        asm volatile("ld.shared.v2.u64 {%0, %1}, [%2];"                         \
            : "=l"(P0), "=l"(P1) : "r"(lo_ + c * 32));                          \
        asm volatile("ld.shared.v2.u64 {%0, %1}, [%2];"                         \
            : "=l"(P2), "=l"(P3) : "r"(lo_ + c * 32 + 16));                     \
        fma2(a0_, P0, EA[4*c  ]); fma2(b0_, P0, EB[4*c  ]); fma2(c0_, P0, EC[4*c  ]); \
        fma2(a1_, P1, EA[4*c+1]); fma2(b1_, P1, EB[4*c+1]); fma2(c1_, P1, EC[4*c+1]); \
        fma2(a0_, P2, EA[4*c+2]); fma2(b0_, P2, EB[4*c+2]); fma2(c0_, P2, EC[4*c+2]); \
        fma2(a1_, P3, EA[4*c+3]); fma2(b1_, P3, EB[4*c+3]); fma2(c1_, P3, EC[4*c+3]); \
    }                                                                           \
    float qA_ = hsum2(a0_, a1_) * ceA_;                                         \
    float qB_ = hsum2(b0_, b1_) * ceB_;                                         \
    float qC_ = hsum2(c0_, c1_) * ceC_;                                         \
    qA_ += __shfl_xor_sync(FULL, qA_, 16);                                      \
    qB_ += __shfl_xor_sync(FULL, qB_, 16);                                      \
    qC_ += __shfl_xor_sync(FULL, qC_, 16);                                      \
    pA_ = qA_; pB_ = qB_; pC_ = qC_;                                            \
    const unsigned st_ = wb_ + stoff;                                           \
    asm volatile("st.shared.f32 [%0], %1;" :: "r"(st_),       "f"(qA_));        \
    asm volatile("st.shared.f32 [%0], %1;" :: "r"(st_ + 64),  "f"(qB_));        \
    asm volatile("st.shared.f32 [%0], %1;" :: "r"(st_ + 128), "f"(qC_));        \
} while (0)

// clamped 3-column emission load for step s (branchless, always in-bounds)
#define LD3(s_, x_, y_, z_) do {                                                \
    int r_ = min((s_), len - 1);                                                \
    const float* p_ = emp + (long)r_ * TT;                                      \
    x_ = __ldg(p_ + cA); y_ = __ldg(p_ + cB); z_ = __ldg(p_ + cC);              \
} while (0)

// 148 blocks x 128 threads: 1 CTA/SM, 1 warp/SMSP. Warp k runs perm[1023-k]
// (long) then, if k < NPAIR, perm[k] (short): pair sums ~= 513 steps for all.
extern "C" __global__ void __launch_bounds__(128)
crf_kernel(const float* __restrict__ em,      // [B,S,T]
           const int*   __restrict__ tags,    // [B,S]
           const float* __restrict__ trans,   // [T,T]
           const float* __restrict__ startt,  // [T]
           const float* __restrict__ endt,    // [T]
           float* __restrict__ out)
{
    const int lane = threadIdx.x & 31;
    const int wid  = threadIdx.x >> 5;
    const int k    = blockIdx.x * 4 + wid;      // 0..591

    // [warp][parity][128 floats]: bytes 0..192 = combined p (48), 256..448 = hi shadow
    __shared__ __align__(16) float p_buf[4][2][128];

    const int j     = lane & 15;
    const int half  = lane >> 4;
    const int rbase = half * 24;
    const unsigned rb4 = (unsigned)(rbase * 4);
    const int cA = j, cB = j + 16, cC = j + 32;

    // ---- E = exp(transitions): this lane's 24 rows x 3 columns ----
    ull EA[12], EB[12], EC[12];
    #pragma unroll
    for (int kk = 0; kk < 12; kk++) {
        int r = rbase + 2 * kk;
        EA[kk] = pack2f(__expf(__ldg(&trans[r * TT + cA])),
                        __expf(__ldg(&trans[(r + 1) * TT + cA])));
        EB[kk] = pack2f(__expf(__ldg(&trans[r * TT + cB])),
                        __expf(__ldg(&trans[(r + 1) * TT + cB])));
        EC[kk] = pack2f(__expf(__ldg(&trans[r * TT + cC])),
                        __expf(__ldg(&trans[(r + 1) * TT + cC])));
    }
    const float eeA = __expf(__ldg(&endt[cA]));
    const float eeB = __expf(__ldg(&endt[cB]));
    const float eeC = __expf(__ldg(&endt[cC]));

    const unsigned pbufb = (unsigned)__cvta_generic_to_shared(&p_buf[wid][0][0]);
    const unsigned stoff = (unsigned)(half * 256 + j * 4);   // hi half -> shadow

    const int npass = (k < NPAIR) ? 2 : 1;
    #pragma unroll 1
    for (int pass = 0; pass < npass; pass++) {
        const int b   = (pass == 0) ? g_perm[BB - 1 - k] : g_perm[k];
        const int len = g_len[b];
        const float* emp = em + (long)b * SS * TT;

        // ---- gold path score ----
        float gold;
        {
            float g = 0.f;
            const long eb = (long)b * SS * TT;
            #pragma unroll 4
            for (int it = 0; it < SS / 32; it++) {
                int t = lane + it * 32;
                if (t < len) {
                    int tg = tags[b * SS + t];
                    if (t == 0) g += __ldg(&startt[tg]) + __ldg(&em[eb + tg]);
                    else {
                        int tp = tags[b * SS + t - 1];
                        g += __ldg(&trans[tg * TT + tp]) + __ldg(&em[eb + (long)t * TT + tg]);
                    }
                    if (t == len - 1) g += __ldg(&endt[tg]);
                }
            }
            gold = warp_sum_f(g);
        }

        // ---- init at t = 0: combined p on ALL lanes (both halves identical) ----
        float pA, pB, pC, sref;
        int esum = 0;
        {
            float a  = __ldg(&startt[cA]) + emp[cA];
            float bb = __ldg(&startt[cB]) + emp[cB];
            float cc = __ldg(&startt[cC]) + emp[cC];
            sref = __shfl_sync(FULL, a, 0);
            pA = __expf(a - sref);
            pB = __expf(bb - sref);
            pC = __expf(cc - sref);
            unsigned s0 = pbufb + stoff;   // parity 0 (hi half writes shadow)
            asm volatile("st.shared.f32 [%0], %1;" :: "r"(s0),       "f"(pA));
            asm volatile("st.shared.f32 [%0], %1;" :: "r"(s0 + 64),  "f"(pB));
            asm volatile("st.shared.f32 [%0], %1;" :: "r"(s0 + 128), "f"(pC));
        }

        // ---- emission register pipeline: rows t .. t+3 in e0..e3 ----
        float e0A, e0B, e0C, e1A, e1B, e1C, e2A, e2B, e2C, e3A, e3B, e3C;
        LD3(1, e0A, e0B, e0C);
        LD3(2, e1A, e1B, e1C);
        LD3(3, e2A, e2B, e2C);
        LD3(4, e3A, e3B, e3C);

        int t = 1;   // stays odd at loop top -> static parities in the body
        #pragma unroll 1
        for (; t + 3 < len; t += 4) {
            float n0A, n0B, n0C, n1A, n1B, n1C, n2A, n2B, n2C, n3A, n3B, n3C;
            LD3(t + 4, n0A, n0B, n0C);
            LD3(t + 5, n1A, n1B, n1C);
            LD3(t + 6, n2A, n2B, n2C);
            LD3(t + 7, n3A, n3B, n3C);

            STEPX(pA, pB, pC, e0A, e0B, e0C,   0u, 512u, 0, t);
            STEPX(pA, pB, pC, e1A, e1B, e1C, 512u,   0u, 1, t + 1);
            STEPX(pA, pB, pC, e2A, e2B, e2C,   0u, 512u, 0, t + 2);
            STEPX(pA, pB, pC, e3A, e3B, e3C, 512u,   0u, 1, t + 3);

            e0A = n0A; e0B = n0B; e0C = n0C;
            e1A = n1A; e1B = n1B; e1C = n1C;
            e2A = n2A; e2B = n2B; e2C = n2C;
            e3A = n3A; e3B = n3B; e3C = n3C;
        }
        // ---- tail: up to 3 steps, parities still static (t odd here) ----
        if (t < len) { STEPX(pA, pB, pC, e0A, e0B, e0C,   0u, 512u, 0, t); t++; }
        if (t < len) { STEPX(pA, pB, pC, e1A, e1B, e1C, 512u,   0u, 1, t); t++; }
        if (t < len) { STEPX(pA, pB, pC, e2A, e2B, e2C,   0u, 512u, 0, t); t++; }

        // ---- final: fwd = sref + esum*ln2 + log(sum_c p_c * exp(end_c)) ----
        {
            float v = pA * eeA + pB * eeB + pC * eeC;
            float ssum = warp_sum_f(v) * 0.5f;   // both halves hold combined p
            if (lane == 0)
                g_scratch[b] = (double)sref + (double)esum * LN2
                             + (double)__logf(ssum) - (double)gold;
        }
    }

    // ---- fused mean: last block reduces ----
    __syncthreads();
    __shared__ bool is_last;
    if (threadIdx.x == 0) {
        __threadfence();
        unsigned r = atomicAdd(&g_count, 1u);
        is_last = (r == gridDim.x - 1);
    }
    __syncthreads();
    if (is_last) {
        __threadfence();
        double s = 0.0;
        for (int i = threadIdx.x; i < BB; i += 128) s += g_scratch[i];
        __shared__ double sh[128];
        sh[threadIdx.x] = s;
        __syncthreads();
        #pragma unroll
        for (int o = 64; o; o >>= 1) {
            if (threadIdx.x < o) sh[threadIdx.x] += sh[threadIdx.x + o];
            __syncthreads();
        }
        if (threadIdx.x == 0) {
            out[0] = (float)(sh[0] / (double)BB);
            g_count = 0;   // reset for next graph replay
        }
    }
}

extern "C" void kernel_launch(void* const* d_in, const int* in_sizes, int n_in,
                              void* d_out, int out_size) {
    const float* em     = (const float*)d_in[0];
    const int*   tags   = (const int*)d_in[1];
    const float* mask   = (const float*)d_in[2];
    const float* trans  = (const float*)d_in[3];
    const float* startt = (const float*)d_in[4];
    const float* endt   = (const float*)d_in[5];
    float* out = (float*)d_out;

    prep_kernel<<<1, 1024>>>(mask);
    crf_kernel<<<148, 128>>>(em, tags, trans, startt, endt, out);
}

// round 17
// speedup vs baseline: 1.9654x; 1.0414x over previous
#include <cuda_runtime.h>
#include <cuda_bf16.h>
#include <cstdint>

#define BB 1024
#define SS 512
#define TT 48
#define FULL 0xFFFFFFFFu
#define NPAIR 432          // warp-ranks 0..431 run two half-jobs; 432..591 one
#define LN2 0.69314718055994530942

typedef unsigned long long ull;

__device__ double g_scratch[BB];
__device__ unsigned int g_count = 0;
__device__ int g_len[BB];
__device__ int g_perm[BB];
__device__ float g_hv[BB][2][48];   // per-batch fwd(0)/bwd(1) half-state
__device__ float g_hsref[BB];       // fwd shift
__device__ int   g_hesum[BB][2];    // power-of-2 rescale exponents
__device__ float g_gold[BB];

__device__ __forceinline__ ull pack2f(float a, float b) {
    ull r;
    asm("mov.b64 %0, {%1, %2};" : "=l"(r) : "f"(a), "f"(b));
    return r;
}
__device__ __forceinline__ void unpack2f(ull v, float& lo, float& hi) {
    asm("mov.b64 {%0, %1}, %2;" : "=f"(lo), "=f"(hi) : "l"(v));
}
__device__ __forceinline__ void fma2(ull& acc, ull a, ull b) {
    asm("fma.rn.f32x2 %0, %1, %2, %0;" : "+l"(acc) : "l"(a), "l"(b));
}
__device__ __forceinline__ ull add2(ull a, ull b) {
    ull r;
    asm("add.rn.f32x2 %0, %1, %2;" : "=l"(r) : "l"(a), "l"(b));
    return r;
}
__device__ __forceinline__ float hsum2(ull a, ull b) {
    ull u = add2(a, b);
    float lo, hi;
    unpack2f(u, lo, hi);
    return lo + hi;
}
__device__ __forceinline__ float warp_sum_f(float v) {
    #pragma unroll
    for (int o = 16; o; o >>= 1) v += __shfl_xor_sync(FULL, v, o);
    return v;
}

// ---------- fused prepass: lengths (binary search) + counting sort ----------
extern "C" __global__ void __launch_bounds__(1024)
prep_kernel(const float* __restrict__ mask) {
    const int b = threadIdx.x;
    int lo = 0, hi = SS;
    #pragma unroll
    for (int it = 0; it < 9; it++) {
        int mid = (lo + hi) >> 1;
        bool one = __ldg(&mask[b * SS + mid]) > 0.5f;
        lo = one ? mid : lo;
        hi = one ? hi : mid;
    }
    const int len = lo + 1;
    g_len[b] = len;

    __shared__ int cnt[SS + 1];
    __shared__ int scn[SS + 1];
    if (threadIdx.x <= SS) cnt[threadIdx.x] = 0;
    __syncthreads();
    atomicAdd(&cnt[len], 1);
    __syncthreads();
    if (threadIdx.x <= SS) scn[threadIdx.x] = cnt[threadIdx.x];
    __syncthreads();
    #pragma unroll
    for (int off = 1; off <= SS; off <<= 1) {
        int v = 0;
        if (threadIdx.x <= SS && threadIdx.x >= off) v = scn[threadIdx.x - off];
        __syncthreads();
        if (threadIdx.x <= SS) scn[threadIdx.x] += v;
        __syncthreads();
    }
    if (threadIdx.x <= SS) cnt[threadIdx.x] = scn[threadIdx.x] - cnt[threadIdx.x];
    __syncthreads();
    int r = atomicAdd(&cnt[len], 1);
    g_perm[r] = b;                      // ascending by length
}

// One recurrence step — EXACT round-14 body. Writer-side shfl.xor(16) combine,
// compile-time parity offsets, power-of-2 rescale every 4 steps (static DORESC).
#define STEPX(pA_, pB_, pC_, exA_, exB_, exC_, RBOFF_, WBOFF_, DORESC_, t_) do { \
    const unsigned rb_ = pbufb + (RBOFF_);                                      \
    const unsigned wb_ = pbufb + (WBOFF_);                                      \
    float ceA_ = __expf(exA_);                                                  \
    float ceB_ = __expf(exB_);                                                  \
    float ceC_ = __expf(exC_);                                                  \
    if (DORESC_ && (((t_) & 3) == 0)) {                                         \
        float r0_;                                                              \
        asm volatile("ld.shared.f32 %0, [%1];" : "=f"(r0_) : "r"(rb_));         \
        int e_ = ((__float_as_int(r0_) >> 23) & 0xFF) - 127;                    \
        float sc_ = __int_as_float((127 - e_) << 23);                           \
        ceA_ *= sc_; ceB_ *= sc_; ceC_ *= sc_;                                  \
        esum += e_;                                                             \
    }                                                                           \
    ull a0_ = 0ull, a1_ = 0ull, b0_ = 0ull, b1_ = 0ull, c0_ = 0ull, c1_ = 0ull; \
    const unsigned lo_ = rb_ + rb4;                                             \
    _Pragma("unroll")                                                           \
    for (int c = 0; c < 3; c++) {                                               \
        ull P0, P1, P2, P3;                                                     \
        asm volatile("ld.shared.v2.u64 {%0, %1}, [%2];"                         \
            : "=l"(P0), "=l"(P1) : "r"(lo_ + c * 32));                          \
        asm volatile("ld.shared.v2.u64 {%0, %1}, [%2];"                         \
            : "=l"(P2), "=l"(P3) : "r"(lo_ + c * 32 + 16));                     \
        fma2(a0_, P0, EA[4*c  ]); fma2(b0_, P0, EB[4*c  ]); fma2(c0_, P0, EC[4*c  ]); \
        fma2(a1_, P1, EA[4*c+1]); fma2(b1_, P1, EB[4*c+1]); fma2(c1_, P1, EC[4*c+1]); \
        fma2(a0_, P2, EA[4*c+2]); fma2(b0_, P2, EB[4*c+2]); fma2(c0_, P2, EC[4*c+2]); \
        fma2(a1_, P3, EA[4*c+3]); fma2(b1_, P3, EB[4*c+3]); fma2(c1_, P3, EC[4*c+3]); \
    }                                                                           \
    float qA_ = hsum2(a0_, a1_) * ceA_;                                         \
    float qB_ = hsum2(b0_, b1_) * ceB_;                                         \
    float qC_ = hsum2(c0_, c1_) * ceC_;                                         \
    qA_ += __shfl_xor_sync(FULL, qA_, 16);                                      \
    qB_ += __shfl_xor_sync(FULL, qB_, 16);                                      \
    qC_ += __shfl_xor_sync(FULL, qC_, 16);                                      \
    pA_ = qA_; pB_ = qB_; pC_ = qC_;                                            \
    const unsigned st_ = wb_ + stoff;                                           \
    asm volatile("st.shared.f32 [%0], %1;" :: "r"(st_),       "f"(qA_));        \
    asm volatile("st.shared.f32 [%0], %1;" :: "r"(st_ + 64),  "f"(qB_));        \
    asm volatile("st.shared.f32 [%0], %1;" :: "r"(st_ + 128), "f"(qC_));        \
} while (0)

// forward emission load: row min(s, len-1), always real (clamped dummies only
// feed steps that never execute)
#define LD3F(s_, x_, y_, z_) do {                                               \
    int r_ = min((s_), len - 1);                                                \
    const float* p_ = emp + (long)r_ * TT;                                      \
    x_ = __ldg(p_ + cA); y_ = __ldg(p_ + cB); z_ = __ldg(p_ + cC);              \
} while (0)

// backward emission load: row len-1-min(s,ns); zeroed for s >= ns so the final
// step (s == ns) is the unit-ce matvec y_h = E u_{h+1} (branchless selects)
#define LD3B(s_, x_, y_, z_) do {                                               \
    int q_ = min((s_), ns);                                                     \
    const float* p_ = emp + (long)(len - 1 - q_) * TT;                          \
    float xv_ = __ldg(p_ + cA), yv_ = __ldg(p_ + cB), zv_ = __ldg(p_ + cC);     \
    bool kp_ = (s_) < ns;                                                       \
    x_ = kp_ ? xv_ : 0.f; y_ = kp_ ? yv_ : 0.f; z_ = kp_ ? zv_ : 0.f;           \
} while (0)

// 148 blocks x 256 threads (8 warps -> 2 warps/SMSP, one fwd + one same-size
// fwd neighbor since direction is PER BLOCK: bid<74 fwd, else bwd; each SM's
// L0 I$ holds a single loop). Warp rank k = local_bid*8 + wid runs the
// half-jobs of perm[1023-k] and (k<NPAIR) perm[k]: ~256 steps per warp, max
// job 256 -> makespan ~256 steps at ~390cyc (2/SMSP) instead of 512 at 300.
// fwd computes alpha_h (h=len>>1) + gold; bwd computes y_h via u-recurrence
// with E transposed and a final unit-ce matvec (round-15 proven algebra).
extern "C" __global__ void __launch_bounds__(256)
half_kernel(const float* __restrict__ em,
            const int*   __restrict__ tags,
            const float* __restrict__ trans,
            const float* __restrict__ startt,
            const float* __restrict__ endt)
{
    const int lane = threadIdx.x & 31;
    const int wid  = threadIdx.x >> 5;
    const bool isfwd = (blockIdx.x < 74);
    const int k = (isfwd ? blockIdx.x : blockIdx.x - 74) * 8 + wid;   // 0..591
    const int hix = isfwd ? 0 : 1;

    __shared__ __align__(16) float p_buf[8][2][128];

    const int j     = lane & 15;
    const int half  = lane >> 4;
    const int rbase = half * 24;
    const unsigned rb4 = (unsigned)(rbase * 4);
    const int cA = j, cB = j + 16, cC = j + 32;
    const unsigned stoff = (unsigned)(half * 256 + j * 4);

    // E: fwd contracts first index of exp(trans); bwd uses the transpose
    ull EA[12], EB[12], EC[12];
    #pragma unroll
    for (int kk = 0; kk < 12; kk++) {
        int r0 = rbase + 2 * kk, r1 = r0 + 1;
        int iA0 = isfwd ? (r0 * TT + cA) : (cA * TT + r0);
        int iA1 = isfwd ? (r1 * TT + cA) : (cA * TT + r1);
        int iB0 = isfwd ? (r0 * TT + cB) : (cB * TT + r0);
        int iB1 = isfwd ? (r1 * TT + cB) : (cB * TT + r1);
        int iC0 = isfwd ? (r0 * TT + cC) : (cC * TT + r0);
        int iC1 = isfwd ? (r1 * TT + cC) : (cC * TT + r1);
        EA[kk] = pack2f(__expf(__ldg(&trans[iA0])), __expf(__ldg(&trans[iA1])));
        EB[kk] = pack2f(__expf(__ldg(&trans[iB0])), __expf(__ldg(&trans[iB1])));
        EC[kk] = pack2f(__expf(__ldg(&trans[iC0])), __expf(__ldg(&trans[iC1])));
    }

    const unsigned pbufb = (unsigned)__cvta_generic_to_shared(&p_buf[wid][0][0]);
    const int npass = (k < NPAIR) ? 2 : 1;

    if (isfwd) {
        #pragma unroll 1
        for (int pass = 0; pass < npass; pass++) {
            const int b   = (pass == 0) ? g_perm[BB - 1 - k] : g_perm[k];
            const int len = g_len[b];
            const int ns  = len >> 1;        // fwd steps 1..ns -> alpha_h
            const int lim = ns + 1;
            const float* emp = em + (long)b * SS * TT;

            // ---- gold path score ----
            {
                float g = 0.f;
                const long eb = (long)b * SS * TT;
                #pragma unroll 4
                for (int it = 0; it < SS / 32; it++) {
                    int t = lane + it * 32;
                    if (t < len) {
                        int tg = tags[b * SS + t];
                        if (t == 0) g += __ldg(&startt[tg]) + __ldg(&em[eb + tg]);
                        else {
                            int tp = tags[b * SS + t - 1];
                            g += __ldg(&trans[tg * TT + tp]) + __ldg(&em[eb + (long)t * TT + tg]);
                        }
                        if (t == len - 1) g += __ldg(&endt[tg]);
                    }
                }
                float gold = warp_sum_f(g);
                if (lane == 0) g_gold[b] = gold;
            }

            // ---- init alpha_0 (product domain, shifted by column-0 score) ----
            float pA, pB, pC, sref;
            int esum = 0;
            {
                float a  = __ldg(&startt[cA]) + emp[cA];
                float bb = __ldg(&startt[cB]) + emp[cB];
                float cc = __ldg(&startt[cC]) + emp[cC];
                sref = __shfl_sync(FULL, a, 0);
                pA = __expf(a - sref);
                pB = __expf(bb - sref);
                pC = __expf(cc - sref);
                unsigned s0 = pbufb + stoff;
                asm volatile("st.shared.f32 [%0], %1;" :: "r"(s0),       "f"(pA));
                asm volatile("st.shared.f32 [%0], %1;" :: "r"(s0 + 64),  "f"(pB));
                asm volatile("st.shared.f32 [%0], %1;" :: "r"(s0 + 128), "f"(pC));
            }

            float e0A, e0B, e0C, e1A, e1B, e1C, e2A, e2B, e2C, e3A, e3B, e3C;
            LD3F(1, e0A, e0B, e0C);
            LD3F(2, e1A, e1B, e1C);
            LD3F(3, e2A, e2B, e2C);
            LD3F(4, e3A, e3B, e3C);

            int t = 1;
            #pragma unroll 1
            for (; t + 3 < lim; t += 4) {
                float n0A, n0B, n0C, n1A, n1B, n1C, n2A, n2B, n2C, n3A, n3B, n3C;
                LD3F(t + 4, n0A, n0B, n0C);
                LD3F(t + 5, n1A, n1B, n1C);
                LD3F(t + 6, n2A, n2B, n2C);
                LD3F(t + 7, n3A, n3B, n3C);

                STEPX(pA, pB, pC, e0A, e0B, e0C,   0u, 512u, 0, t);
                STEPX(pA, pB, pC, e1A, e1B, e1C, 512u,   0u, 1, t + 1);
                STEPX(pA, pB, pC, e2A, e2B, e2C,   0u, 512u, 0, t + 2);
                STEPX(pA, pB, pC, e3A, e3B, e3C, 512u,   0u, 1, t + 3);

                e0A = n0A; e0B = n0B; e0C = n0C;
                e1A = n1A; e1B = n1B; e1C = n1C;
                e2A = n2A; e2B = n2B; e2C = n2C;
                e3A = n3A; e3B = n3B; e3C = n3C;
            }
            if (t < lim) { STEPX(pA, pB, pC, e0A, e0B, e0C,   0u, 512u, 0, t); t++; }
            if (t < lim) { STEPX(pA, pB, pC, e1A, e1B, e1C, 512u,   0u, 1, t); t++; }
            if (t < lim) { STEPX(pA, pB, pC, e2A, e2B, e2C,   0u, 512u, 0, t); t++; }

            if (lane < 16) {
                float* hv = &g_hv[b][0][0];
                hv[cA] = pA; hv[cB] = pB; hv[cC] = pC;
            }
            if (lane == 0) { g_hesum[b][0] = esum; g_hsref[b] = sref; }
        }
    } else {
        #pragma unroll 1
        for (int pass = 0; pass < npass; pass++) {
            const int b   = (pass == 0) ? g_perm[BB - 1 - k] : g_perm[k];
            const int len = g_len[b];
            const int h   = len >> 1;
            const int ns  = len - 1 - h;     // bwd steps 1..ns (last = unit ce)
            const int lim = ns + 1;
            const float* emp = em + (long)b * SS * TT;

            // ---- init u_{len-1} = exp(end + em_{len-1}) (em skipped if ns==0) ----
            float pA, pB, pC;
            int esum = 0;
            {
                const float* q = emp + (long)(len - 1) * TT;
                float g0 = (ns > 0) ? __ldg(q + cA) : 0.f;
                float g1 = (ns > 0) ? __ldg(q + cB) : 0.f;
                float g2 = (ns > 0) ? __ldg(q + cC) : 0.f;
                pA = __expf(__ldg(&endt[cA]) + g0);
                pB = __expf(__ldg(&endt[cB]) + g1);
                pC = __expf(__ldg(&endt[cC]) + g2);
                unsigned s0 = pbufb + stoff;
                asm volatile("st.shared.f32 [%0], %1;" :: "r"(s0),       "f"(pA));
                asm volatile("st.shared.f32 [%0], %1;" :: "r"(s0 + 64),  "f"(pB));
                asm volatile("st.shared.f32 [%0], %1;" :: "r"(s0 + 128), "f"(pC));
            }

            float e0A, e0B, e0C, e1A, e1B, e1C, e2A, e2B, e2C, e3A, e3B, e3C;
            LD3B(1, e0A, e0B, e0C);
            LD3B(2, e1A, e1B, e1C);
            LD3B(3, e2A, e2B, e2C);
            LD3B(4, e3A, e3B, e3C);

            int t = 1;
            #pragma unroll 1
            for (; t + 3 < lim; t += 4) {
                float n0A, n0B, n0C, n1A, n1B, n1C, n2A, n2B, n2C, n3A, n3B, n3C;
                LD3B(t + 4, n0A, n0B, n0C);
                LD3B(t + 5, n1A, n1B, n1C);
                LD3B(t + 6, n2A, n2B, n2C);
                LD3B(t + 7, n3A, n3B, n3C);

                STEPX(pA, pB, pC, e0A, e0B, e0C,   0u, 512u, 0, t);
                STEPX(pA, pB, pC, e1A, e1B, e1C, 512u,   0u, 1, t + 1);
                STEPX(pA, pB, pC, e2A, e2B, e2C,   0u, 512u, 0, t + 2);
                STEPX(pA, pB, pC, e3A, e3B, e3C, 512u,   0u, 1, t + 3);

                e0A = n0A; e0B = n0B; e0C = n0C;
                e1A = n1A; e1B = n1B; e1C = n1C;
                e2A = n2A; e2B = n2B; e2C = n2C;
                e3A = n3A; e3B = n3B; e3C = n3C;
            }
            if (t < lim) { STEPX(pA, pB, pC, e0A, e0B, e0C,   0u, 512u, 0, t); t++; }
            if (t < lim) { STEPX(pA, pB, pC, e1A, e1B, e1C, 512u,   0u, 1, t); t++; }
            if (t < lim) { STEPX(pA, pB, pC, e2A, e2B, e2C,   0u, 512u, 0, t); t++; }

            if (lane < 16) {
                float* hv = &g_hv[b][1][0];
                hv[cA] = pA; hv[cB] = pB; hv[cC] = pC;
            }
            if (lane == 0) g_hesum[b][1] = esum;
        }
    }
}

// combine: logZ = sref + (esum_f+esum_b)*ln2 + log(sum_j alpha_h . y_h); mean
extern "C" __global__ void __launch_bounds__(128)
comb_kernel(float* __restrict__ out) {
    const int lane = threadIdx.x & 31;
    const int wid  = threadIdx.x >> 5;
    const int b    = blockIdx.x * 4 + wid;   // grid 256 -> 0..1023

    float v = 0.f;
    if (lane < 16) {
        const float* pf = &g_hv[b][0][0];
        const float* pb = &g_hv[b][1][0];
        int c0 = lane, c1 = lane + 16, c2 = lane + 32;
        v = pf[c0] * pb[c0] + pf[c1] * pb[c1] + pf[c2] * pb[c2];
    }
    float ssum = warp_sum_f(v);
    if (lane == 0) {
        double logz = (double)g_hsref[b]
                    + (double)(g_hesum[b][0] + g_hesum[b][1]) * LN2
                    + (double)__logf(ssum);
        g_scratch[b] = logz - (double)g_gold[b];
    }

    __syncthreads();
    __shared__ bool is_last;
    if (threadIdx.x == 0) {
        __threadfence();
        unsigned r = atomicAdd(&g_count, 1u);
        is_last = (r == gridDim.x - 1);
    }
    __syncthreads();
    if (is_last) {
        __threadfence();
        double s = 0.0;
        for (int i = threadIdx.x; i < BB; i += 128) s += g_scratch[i];
        __shared__ double sh[128];
        sh[threadIdx.x] = s;
        __syncthreads();
        #pragma unroll
        for (int o = 64; o; o >>= 1) {
            if (threadIdx.x < o) sh[threadIdx.x] += sh[threadIdx.x + o];
            __syncthreads();
        }
        if (threadIdx.x == 0) {
            out[0] = (float)(sh[0] / (double)BB);
            g_count = 0;   // reset for next graph replay
        }
    }
}

extern "C" void kernel_launch(void* const* d_in, const int* in_sizes, int n_in,
                              void* d_out, int out_size) {
    const float* em     = (const float*)d_in[0];
    const int*   tags   = (const int*)d_in[1];
    const float* mask   = (const float*)d_in[2];
    const float* trans  = (const float*)d_in[3];
    const float* startt = (const float*)d_in[4];
    const float* endt   = (const float*)d_in[5];
    float* out = (float*)d_out;

    prep_kernel<<<1, 1024>>>(mask);
    half_kernel<<<148, 256>>>(em, tags, trans, startt, endt);
    comb_kernel<<<256, 128>>>(out);
}